// round 5
// baseline (speedup 1.0000x reference)
#include <cuda_runtime.h>

// EMA scan h_t = a*x_t + (1-a)*h_{t-1}, T innermost. Warp-cooperative,
// fully coalesced, one warp per row.
//
// R5: 4-tile unroll (512 elems/iter). All 4 LDG.128 are independent of the
// scan results and batch at the loop top -> 2x outstanding load bytes per
// warp (~25KB/SM in flight, matching the latency-BW product). Truncated
// 3-step Kogge-Stone scan per tile (dropped terms weighted <= 0.6^32).

#define A    0.4f
#define OMA  0.6f
#define OMA2 0.36f
#define OMA3 0.216f
#define OMA4 0.1296f
#define FULL 0xFFFFFFFFu
#define UN   4

__device__ __forceinline__ void tile_prefix(float4 v, float* s)
{
    s[0] = A * v.x;
    s[1] = fmaf(A, v.y, OMA * s[0]);
    s[2] = fmaf(A, v.z, OMA * s[1]);
    s[3] = fmaf(A, v.w, OMA * s[2]);
}

// truncated inclusive scan, decay 0.6^4 per lane (3 steps; trunc err ~8e-8)
__device__ __forceinline__ float tile_scan(float s3, int lane)
{
    float I = s3;
    float u;
    u = __shfl_up_sync(FULL, I, 1);
    if (lane >= 1) I = fmaf(OMA4, u, I);            // 0.6^4
    u = __shfl_up_sync(FULL, I, 2);
    if (lane >= 2) I = fmaf(0.01679616f, u, I);     // 0.6^8
    u = __shfl_up_sync(FULL, I, 4);
    if (lane >= 4) I = fmaf(2.82110990e-4f, u, I);  // 0.6^16
    return I;
}

__global__ void __launch_bounds__(256) ema_warp_kernel(
    const float* __restrict__ x,
    const float* __restrict__ h0,
    float* __restrict__ y,
    int T, int rows)
{
    int gwarp = (blockIdx.x * blockDim.x + threadIdx.x) >> 5;
    int lane  = threadIdx.x & 31;
    if (gwarp >= rows) return;

    const float4* xr = reinterpret_cast<const float4*>(x + (size_t)gwarp * T);
    float4*       yr = reinterpret_cast<float4*>(y + (size_t)gwarp * T);

    float h = h0[gwarp];

    float d4L = __powf(OMA4, (float)lane);      // 0.6^(4*lane)
    const float d128 = 2.4633073e-29f;          // 0.6^128

    int niter = T / (128 * UN);                 // 8
    for (int t = 0; t < niter; t++) {
        int base = t * (32 * UN) + lane;

        // batched independent loads (front of iteration -> max MLP)
        float4 v[UN];
        #pragma unroll
        for (int k = 0; k < UN; k++) v[k] = xr[base + 32 * k];

        // independent per-tile prefixes + scans (4 parallel chains)
        float s[UN][4], I[UN], Bv[UN], I31[UN];
        #pragma unroll
        for (int k = 0; k < UN; k++) tile_prefix(v[k], s[k]);
        #pragma unroll
        for (int k = 0; k < UN; k++) I[k] = tile_scan(s[k][3], lane);
        #pragma unroll
        for (int k = 0; k < UN; k++) {
            Bv[k] = __shfl_up_sync(FULL, I[k], 1);
            if (lane == 0) Bv[k] = 0.0f;
            I31[k] = __shfl_sync(FULL, I[k], 31);
        }

        // fold carry through the 4 tiles (1 FMA + 4 FMAs + store per tile)
        #pragma unroll
        for (int k = 0; k < UN; k++) {
            float C = fmaf(d4L, h, Bv[k]);
            float4 o;
            o.x = fmaf(OMA,  C, s[k][0]);
            o.y = fmaf(OMA2, C, s[k][1]);
            o.z = fmaf(OMA3, C, s[k][2]);
            o.w = fmaf(OMA4, C, s[k][3]);
            yr[base + 32 * k] = o;
            h = fmaf(d128, h, I31[k]);
        }
    }
}

extern "C" void kernel_launch(void* const* d_in, const int* in_sizes, int n_in,
                              void* d_out, int out_size)
{
    const float* x  = (const float*)d_in[0];   // inp    [B, D, T]
    const float* h0 = (const float*)d_in[1];   // hidden [B, D, 1]
    float* y = (float*)d_out;

    int rows = in_sizes[1];        // B*D = 8192
    int T = in_sizes[0] / rows;    // 4096

    int threads = 256;             // 8 warps/block -> 8 rows/block
    int blocks = (rows * 32 + threads - 1) / threads;
    ema_warp_kernel<<<blocks, threads>>>(x, h0, y, T, rows);
}

// round 6
// speedup vs baseline: 1.0502x; 1.0502x over previous
#include <cuda_runtime.h>

// EMA scan h_t = a*x_t + (1-a)*h_{t-1}, T innermost. Warp-cooperative,
// fully coalesced.
//
// R6: (a) each row split across 2 warps (half-row = 2048 elems; second half
// warms up over the preceding 32 elems — truncation 0.6^32 ~ 8e-8);
// (b) 2-stage software pipeline so next iteration's 2 loads overlap current
// compute without front-batching >2 LDGs (avoids the B300 multi-CTA-spread
// penalty seen at MLP_p1=4); (c) regs capped at 32 for full occupancy.

#define A    0.4f
#define OMA  0.6f
#define OMA2 0.36f
#define OMA3 0.216f
#define OMA4 0.1296f
#define FULL 0xFFFFFFFFu

__device__ __forceinline__ void tile_prefix(float4 v, float& s0, float& s1,
                                            float& s2, float& s3)
{
    s0 = A * v.x;
    s1 = fmaf(A, v.y, OMA * s0);
    s2 = fmaf(A, v.z, OMA * s1);
    s3 = fmaf(A, v.w, OMA * s2);
}

// truncated inclusive scan, decay 0.6^4 per lane (3 steps; trunc err ~8e-8)
__device__ __forceinline__ float tile_scan(float s3, int lane)
{
    float I = s3, u;
    u = __shfl_up_sync(FULL, I, 1);
    if (lane >= 1) I = fmaf(OMA4, u, I);            // 0.6^4
    u = __shfl_up_sync(FULL, I, 2);
    if (lane >= 2) I = fmaf(0.01679616f, u, I);     // 0.6^8
    u = __shfl_up_sync(FULL, I, 4);
    if (lane >= 4) I = fmaf(2.82110990e-4f, u, I);  // 0.6^16
    return I;
}

__global__ void __launch_bounds__(256, 8) ema_warp_kernel(
    const float* __restrict__ x,
    const float* __restrict__ h0,
    float* __restrict__ y,
    int T, int nunits)
{
    int unit = (blockIdx.x * blockDim.x + threadIdx.x) >> 5;  // (row, half)
    int lane = threadIdx.x & 31;
    if (unit >= nunits) return;

    int row  = unit >> 1;
    int half = unit & 1;
    int H    = T >> 1;                               // 2048
    size_t base = (size_t)row * T + (size_t)half * H;

    const float4* xr = reinterpret_cast<const float4*>(x + base);
    float4*       yr = reinterpret_cast<float4*>(y + base);

    float h;
    if (half == 0) {
        h = h0[row];
    } else {
        // warp-cooperative warmup over preceding 32 elements (decay/lane 0.6)
        float w = x[base - 32 + lane];
        float I = A * w, u;
        u = __shfl_up_sync(FULL, I, 1);  if (lane >= 1)  I = fmaf(OMA,  u, I);
        u = __shfl_up_sync(FULL, I, 2);  if (lane >= 2)  I = fmaf(OMA2, u, I);
        u = __shfl_up_sync(FULL, I, 4);  if (lane >= 4)  I = fmaf(OMA4, u, I);
        u = __shfl_up_sync(FULL, I, 8);  if (lane >= 8)  I = fmaf(0.01679616f, u, I);   // 0.6^8
        u = __shfl_up_sync(FULL, I, 16); if (lane >= 16) I = fmaf(2.82110990e-4f, u, I);// 0.6^16
        h = __shfl_sync(FULL, I, 31);    // 0.6^32*h_true term dropped (~8e-8)
    }

    float d4L = __powf(OMA4, (float)lane);      // 0.6^(4*lane)
    const float d128 = 2.4633073e-29f;          // 0.6^128

    int niter = H / 256;                        // 8
    // software pipeline: stage loads for iteration 0
    float4 va = xr[lane];
    float4 vb = xr[32 + lane];

    #pragma unroll 1
    for (int t = 0; t < niter; t++) {
        // prefetch next iteration's loads (overlap with compute below)
        float4 na, nb;
        if (t + 1 < niter) {
            na = xr[(t + 1) * 64 + lane];
            nb = xr[(t + 1) * 64 + 32 + lane];
        }

        float a0, a1, a2, a3, b0, b1, b2, b3;
        tile_prefix(va, a0, a1, a2, a3);
        tile_prefix(vb, b0, b1, b2, b3);

        float Ia = tile_scan(a3, lane);
        float Ib = tile_scan(b3, lane);

        float Ba = __shfl_up_sync(FULL, Ia, 1); if (lane == 0) Ba = 0.0f;
        float Bb = __shfl_up_sync(FULL, Ib, 1); if (lane == 0) Bb = 0.0f;
        float I31a = __shfl_sync(FULL, Ia, 31);
        float I31b = __shfl_sync(FULL, Ib, 31);

        float Ca = fmaf(d4L, h, Ba);
        float4 oa;
        oa.x = fmaf(OMA,  Ca, a0);
        oa.y = fmaf(OMA2, Ca, a1);
        oa.z = fmaf(OMA3, Ca, a2);
        oa.w = fmaf(OMA4, Ca, a3);
        yr[t * 64 + lane] = oa;

        float hm = fmaf(d128, h, I31a);

        float Cb = fmaf(d4L, hm, Bb);
        float4 ob;
        ob.x = fmaf(OMA,  Cb, b0);
        ob.y = fmaf(OMA2, Cb, b1);
        ob.z = fmaf(OMA3, Cb, b2);
        ob.w = fmaf(OMA4, Cb, b3);
        yr[t * 64 + 32 + lane] = ob;

        h = fmaf(d128, hm, I31b);

        va = na; vb = nb;
    }
}

extern "C" void kernel_launch(void* const* d_in, const int* in_sizes, int n_in,
                              void* d_out, int out_size)
{
    const float* x  = (const float*)d_in[0];   // inp    [B, D, T]
    const float* h0 = (const float*)d_in[1];   // hidden [B, D, 1]
    float* y = (float*)d_out;

    int rows = in_sizes[1];        // B*D = 8192
    int T = in_sizes[0] / rows;    // 4096
    int nunits = rows * 2;         // 2 warps per row

    int threads = 256;             // 8 warps/block
    int blocks = (nunits * 32 + threads - 1) / threads;
    ema_warp_kernel<<<blocks, threads>>>(x, h0, y, T, nunits);
}